// round 1
// baseline (speedup 1.0000x reference)
#include <cuda_runtime.h>
#include <cstdint>

#define Bsz 32
#define Cc  64
#define Hh  64
#define Ww  64
#define OCt 128
#define Ho  62
#define Wo  62

#define OCB   8      // output channels per block
#define TILE  32     // 32x32 output tile
#define XT    34     // 34x34 input tile
#define XST   36     // padded row stride (floats)
#define CSTEP 2      // channels staged per sync pair

typedef unsigned long long ull;

__device__ __forceinline__ ull pk(float lo, float hi) {
    ull r;
    asm("mov.b64 %0, {%1, %2};" : "=l"(r) : "f"(lo), "f"(hi));
    return r;
}

__device__ __forceinline__ float2 unpk(ull v) {
    float lo, hi;
    asm("mov.b64 {%0, %1}, %2;" : "=f"(lo), "=f"(hi) : "l"(v));
    return make_float2(lo, hi);
}

// packed fp32x2 FMA: acc = a*b + acc (lane-wise on two packed fp32)
#define FMA2(acc, a, b) \
    asm("fma.rn.f32x2 %0, %1, %2, %0;" : "+l"(acc) : "l"(a), "l"(b))

__global__ __launch_bounds__(256)
void quanv_kernel(const float* __restrict__ x,
                  const float* __restrict__ w,
                  float* __restrict__ out)
{
    __shared__ float  xs[CSTEP][XT][XST];           // 9792 B
    __shared__ float2 ws[OCB][Cc][9];               // 36864 B (weights duplicated (w,w))

    const int tid = threadIdx.x;
    const int tx  = tid & 15;
    const int ty  = tid >> 4;

    const int tileIdx = blockIdx.x;    // 0..3
    const int ocg     = blockIdx.y;    // 0..15
    const int b       = blockIdx.z;    // 0..31

    const int col0 = (tileIdx & 1) * TILE;
    const int row0 = (tileIdx >> 1) * TILE;

    // ---- stage weights for this oc-group, duplicated into float2 ----
    {
        const float* wg = w + (size_t)ocg * OCB * Cc * 9;
        float2* wsf = &ws[0][0][0];
        #pragma unroll 4
        for (int i = tid; i < OCB * Cc * 9; i += 256) {
            float v = wg[i];
            wsf[i] = make_float2(v, v);
        }
    }

    // accumulators: [oc][py], each packs 2 adjacent output cols
    ull acc[OCB][2];
    #pragma unroll
    for (int o = 0; o < OCB; o++) {
        acc[o][0] = 0ull;
        acc[o][1] = 0ull;
    }

    const float* xb = x + (size_t)b * Cc * Hh * Ww;

    for (int cc = 0; cc < Cc; cc += CSTEP) {
        __syncthreads();
        // stage CSTEP channel tiles (guarded scalar loads; edges read 0)
        for (int i = tid; i < CSTEP * XT * XT; i += 256) {
            int ch = i / (XT * XT);
            int j  = i - ch * (XT * XT);
            int r  = j / XT;
            int q  = j - r * XT;
            int gr = row0 + r, gc = col0 + q;
            float v = (gr < Hh && gc < Ww) ? xb[(size_t)(cc + ch) * Hh * Ww + gr * Ww + gc]
                                           : 0.0f;
            xs[ch][r][q] = v;
        }
        __syncthreads();

        #pragma unroll
        for (int ci = 0; ci < CSTEP; ci++) {
            const int c = cc + ci;

            // 4x4 input patch for this thread's 2x2 outputs, packed as col pairs
            // pp[r][kw] = (patch[r][kw], patch[r][kw+1])
            ull pp[4][3];
            #pragma unroll
            for (int r = 0; r < 4; r++) {
                float2 a  = *(const float2*)&xs[ci][2 * ty + r][2 * tx];
                float2 bq = *(const float2*)&xs[ci][2 * ty + r][2 * tx + 2];
                pp[r][0] = pk(a.x, a.y);
                pp[r][1] = pk(a.y, bq.x);
                pp[r][2] = pk(bq.x, bq.y);
            }

            #pragma unroll
            for (int o = 0; o < OCB; o++) {
                const ull* wv = (const ull*)&ws[o][c][0];   // broadcast LDS.64
                #pragma unroll
                for (int kh = 0; kh < 3; kh++) {
                    #pragma unroll
                    for (int kw = 0; kw < 3; kw++) {
                        ull wk = wv[kh * 3 + kw];
                        FMA2(acc[o][0], wk, pp[kh][kw]);       // py=0 uses rows kh
                        FMA2(acc[o][1], wk, pp[kh + 1][kw]);   // py=1 uses rows kh+1
                    }
                }
            }
        }
    }

    // ---- store: layout-bug order: flat = ((oc*B + b)*Ho + ho)*Wo + wo ----
    const int ho0 = row0 + 2 * ty;
    const int wo0 = col0 + 2 * tx;
    if (wo0 < Wo) {   // wo0 even => wo0+1 <= 61 always valid when wo0 < 62
        #pragma unroll
        for (int o = 0; o < OCB; o++) {
            const int oc = ocg * OCB + o;
            #pragma unroll
            for (int py = 0; py < 2; py++) {
                const int ho = ho0 + py;
                if (ho < Ho) {
                    size_t flat = (((size_t)oc * Bsz + b) * Ho + ho) * (size_t)Wo + wo0;
                    *(float2*)(out + flat) = unpk(acc[o][py]);
                }
            }
        }
    }
}

extern "C" void kernel_launch(void* const* d_in, const int* in_sizes, int n_in,
                              void* d_out, int out_size)
{
    const float* x = (const float*)d_in[0];
    const float* w = (const float*)d_in[1];
    float* out     = (float*)d_out;

    dim3 grid(4, OCt / OCB, Bsz);   // (tiles, oc-groups, batch) = (4,16,32)
    quanv_kernel<<<grid, 256>>>(x, w, out);
}

// round 3
// speedup vs baseline: 3.9820x; 3.9820x over previous
#include <cuda_runtime.h>
#include <cstdint>

#define NB   32
#define NC   64
#define NH   64
#define NW   64
#define NOC  128
#define HO   62
#define WO   62
#define NPB  (HO*WO)            // 3844
#define NTILE 31                // ceil(3844/128)
#define NSTG 36                 // K stages of 16 (K = 9*64 = 576)

// tf32-rounded x, same layout as input: [b][c][h][w]
__device__ __align__(16) uint32_t g_x[NB*NC*NH*NW];          // 33.55 MB
// pre-swizzled A (weights): [stage 36][kb 2][oc 128][12 words (8 data + 4 pad)]
__device__ __align__(16) uint32_t g_a[NSTG*2*128*12];        // 442 KB

// ---------------- PTX helpers ----------------
__device__ __forceinline__ uint32_t cvta_s(const void* p) {
    uint32_t a;
    asm("{ .reg .u64 t; cvta.to.shared.u64 t, %1; cvt.u32.u64 %0, t; }" : "=r"(a) : "l"(p));
    return a;
}
__device__ __forceinline__ uint32_t f2tf32(float v) {
    uint32_t d;
    asm("cvt.rna.tf32.f32 %0, %1;" : "=r"(d) : "f"(v));
    return d;
}
#define CP_A16(dst, src) asm volatile("cp.async.cg.shared.global [%0],[%1],16;" :: "r"(dst), "l"(src))
#define CP_A4(dst, src)  asm volatile("cp.async.ca.shared.global [%0],[%1],4;"  :: "r"(dst), "l"(src))
#define CP_COMMIT()      asm volatile("cp.async.commit_group;" ::: "memory")
#define CP_WAIT0()       asm volatile("cp.async.wait_group 0;" ::: "memory")
#define CP_WAIT1()       asm volatile("cp.async.wait_group 1;" ::: "memory")

__device__ __forceinline__ void mma_tf32(float* c, const uint32_t* a, const uint32_t* b) {
    asm volatile(
        "mma.sync.aligned.m16n8k8.row.col.f32.tf32.tf32.f32 "
        "{%0,%1,%2,%3},{%4,%5,%6,%7},{%8,%9},{%0,%1,%2,%3};"
        : "+f"(c[0]), "+f"(c[1]), "+f"(c[2]), "+f"(c[3])
        : "r"(a[0]), "r"(a[1]), "r"(a[2]), "r"(a[3]), "r"(b[0]), "r"(b[1]));
}

// ---------------- prep kernels ----------------
__global__ void prep_x(const float* __restrict__ x) {
    int i = blockIdx.x * 256 + threadIdx.x;
    g_x[i] = f2tf32(x[i]);
}

__global__ void prep_w(const float* __restrict__ w) {
    int idx = blockIdx.x * 256 + threadIdx.x;   // 110592
    int s     = idx / 3072;
    int r     = idx - s * 3072;
    int kb    = r / 1536;
    int r2    = r - kb * 1536;
    int oc    = r2 / 12;
    int kslot = r2 - oc * 12;
    uint32_t val = 0;
    if (kslot < 8) {
        int c   = (s & 3) * 16 + kb * 8 + kslot;
        int off = s >> 2;
        val = f2tf32(w[oc * 576 + c * 9 + off]);
    }
    g_a[idx] = val;
}

// ---------------- main kernel ----------------
// SMEM: A double buf [2][3072] words @0, B double buf [2][2176] words @6144
#define SA_WORDS 3072       // 2 kb * 128 oc * 12
#define SB_WORDS 2176       // 16 kk * 136
#define SB_OFF   6144

__global__ __launch_bounds__(256, 2) void conv_main(float* __restrict__ out) {
    __shared__ __align__(16) uint32_t sm[2*SA_WORDS + 2*SB_WORDS];   // 41984 B

    const int tid  = threadIdx.x;
    const int lane = tid & 31;
    const int warp = tid >> 5;
    const int wm   = warp >> 2;        // 0..1 : oc half
    const int wn   = warp & 3;         // 0..3 : n quarter

    const int bx = blockIdx.x;         // 0..30 : position tile
    const int b  = blockIdx.y;         // batch
    const int n0 = bx * 128;

    const uint32_t smem_b = cvta_s(sm);

    // -------- per-thread copy descriptors --------
    // A copy: 768 x 16B per stage, 3 per thread (contiguous)
    const uint32_t a_dst0 = smem_b + (uint32_t)tid * 16;           // +k*4096B, stage sel
    const uint32_t* a_src0 = g_a + tid * 4;

    // B copy: 2048 x 4B per stage, 8 per thread
    // e = tid + j*256 ; kk = e>>7 ; nl = e&127
    const uint32_t* xb = g_x + (size_t)b * (NC*NH*NW);
    uint32_t b_dst[8];
    const uint32_t* b_src[8];
    #pragma unroll
    for (int j = 0; j < 8; ++j) {
        int e  = tid + j * 256;
        int kk = e >> 7;
        int nl = e & 127;
        int n  = n0 + nl; if (n > NPB-1) n = NPB-1;   // clamp (garbage never stored)
        int ho = n / WO;
        int wo = n - ho * WO;
        b_dst[j] = smem_b + (uint32_t)(SB_OFF + kk * 136 + nl) * 4;
        b_src[j] = xb + kk * (NH*NW) + ho * NW + wo;
    }

    // -------- accumulators --------
    float acc[4][4][4];
    #pragma unroll
    for (int mi = 0; mi < 4; ++mi)
        #pragma unroll
        for (int ni = 0; ni < 4; ++ni)
            #pragma unroll
            for (int q = 0; q < 4; ++q) acc[mi][ni][q] = 0.0f;

    // -------- fragment LDS bases (word indices) --------
    const int a_base = (wm * 64 + (lane >> 2)) * 12 + (lane & 3);
    const int b_base = SB_OFF + (lane & 3) * 136 + wn * 32 + (lane >> 2);

    // -------- prefetch stage 0 --------
    {
        #pragma unroll
        for (int q = 0; q < 3; ++q)
            CP_A16(a_dst0 + q * 4096, (const char*)(a_src0 + q * 1024));
        // stage 0: off=0 (kh=0,kw=0), cblk=0
        #pragma unroll
        for (int j = 0; j < 8; ++j)
            CP_A4(b_dst[j], (const char*)b_src[j]);
        CP_COMMIT();
    }

    #pragma unroll 1
    for (int s = 0; s < NSTG; ++s) {
        const int buf  = s & 1;
        const int nbuf = buf ^ 1;
        if (s + 1 < NSTG) {
            const int s1   = s + 1;
            const int off  = s1 >> 2;
            const int kh   = off / 3;
            const int kw   = off - kh * 3;
            const int srcoff = ((s1 & 3) * 16) * (NH*NW) + kh * NW + kw;
            const uint32_t adst = a_dst0 + (uint32_t)nbuf * (SA_WORDS*4);
            const uint32_t* asrc = a_src0 + s1 * SA_WORDS;
            #pragma unroll
            for (int q = 0; q < 3; ++q)
                CP_A16(adst + q * 4096, (const char*)(asrc + q * 1024));
            const uint32_t bshift = (uint32_t)nbuf * (SB_WORDS*4);
            #pragma unroll
            for (int j = 0; j < 8; ++j)
                CP_A4(b_dst[j] + bshift, (const char*)(b_src[j] + srcoff));
            CP_COMMIT();
            CP_WAIT1();
        } else {
            CP_WAIT0();
        }
        __syncthreads();

        const uint32_t* A = sm + buf * SA_WORDS;
        const uint32_t* B = sm + buf * SB_WORDS;   // b_base already includes SB_OFF

        #pragma unroll
        for (int kb = 0; kb < 2; ++kb) {
            uint32_t af[4][4], bf[4][2];
            const int ab = a_base + kb * 1536;
            const int bb = b_base + kb * 8 * 136;
            #pragma unroll
            for (int mi = 0; mi < 4; ++mi) {
                af[mi][0] = A[ab + mi * 192];
                af[mi][1] = A[ab + mi * 192 + 96];
                af[mi][2] = A[ab + mi * 192 + 4];
                af[mi][3] = A[ab + mi * 192 + 100];
            }
            #pragma unroll
            for (int ni = 0; ni < 4; ++ni) {
                bf[ni][0] = B[bb + ni * 8];
                bf[ni][1] = B[bb + ni * 8 + 4 * 136];
            }
            #pragma unroll
            for (int mi = 0; mi < 4; ++mi)
                #pragma unroll
                for (int ni = 0; ni < 4; ++ni)
                    mma_tf32(acc[mi][ni], af[mi], bf[ni]);
        }
        __syncthreads();
    }

    // -------- epilogue --------
    // acc[mi][ni]: rows oc = wm*64+mi*16+lane/4 (+8), cols n = wn*32+ni*8+2*(lane%4)(+1)
    #pragma unroll
    for (int mi = 0; mi < 4; ++mi) {
        #pragma unroll
        for (int ni = 0; ni < 4; ++ni) {
            const int ocr = wm * 64 + mi * 16 + (lane >> 2);
            const int n   = n0 + wn * 32 + ni * 8 + 2 * (lane & 3);
            if (n < NPB) {
                float* p0 = out + ((size_t)ocr * NB + b) * NPB + n;
                *(float2*)p0 = make_float2(acc[mi][ni][0], acc[mi][ni][1]);
                float* p1 = out + ((size_t)(ocr + 8) * NB + b) * NPB + n;
                *(float2*)p1 = make_float2(acc[mi][ni][2], acc[mi][ni][3]);
            }
        }
    }
}

// ---------------- launch ----------------
extern "C" void kernel_launch(void* const* d_in, const int* in_sizes, int n_in,
                              void* d_out, int out_size) {
    const float* x = (const float*)d_in[0];
    const float* w = (const float*)d_in[1];
    float* out = (float*)d_out;

    prep_x<<<(NB*NC*NH*NW)/256, 256>>>(x);
    prep_w<<<(NSTG*2*128*12)/256, 256>>>(w);
    conv_main<<<dim3(NTILE, NB), 256>>>(out);
}

// round 4
// speedup vs baseline: 4.2798x; 1.0748x over previous
#include <cuda_runtime.h>
#include <cstdint>

#define NB   32
#define NC   64
#define NH   64
#define NW   64
#define NOC  128
#define HO   62
#define WO   62
#define NPB  (HO*WO)            // 3844
#define NTILE 31
#define NSTG 36                 // K stages of 16 (K = 9*64)

// tf32-rounded x, layout [b][c][h][w]
__device__ __align__(16) uint32_t g_x[NB*NC*NH*NW];          // 33.55 MB
// pre-arranged A: [stage 36][kb 2][oc 128][pair 4][2]  (pair p holds k'=p, k'=p+4)
__device__ __align__(16) uint32_t g_a2[NSTG*2048];           // 294.9 KB

// ---- SMEM word geometry (per pipeline buffer) ----
#define AW     2048             // A stage words: 2 kb * 128 oc * 8
#define BKQ    264              // B words per kq row (256 data + 8 pad; 132 % 16 == 4)
#define BKB    (4*BKQ)          // 1056
#define BW     (2*BKB)          // 2112
#define STGW   (AW + BW)        // 4160 words per buffer
#define NBUF   3
#define SMEMB  (NBUF*STGW*4)    // 49920 bytes

// ---------------- PTX helpers ----------------
__device__ __forceinline__ uint32_t cvta_s(const void* p) {
    uint32_t a;
    asm("{ .reg .u64 t; cvta.to.shared.u64 t, %1; cvt.u32.u64 %0, t; }" : "=r"(a) : "l"(p));
    return a;
}
__device__ __forceinline__ uint32_t f2tf32(float v) {
    uint32_t d;
    asm("cvt.rna.tf32.f32 %0, %1;" : "=r"(d) : "f"(v));
    return d;
}
__device__ __forceinline__ uint2 lds64(uint32_t addr) {
    uint2 v;
    asm volatile("ld.shared.v2.b32 {%0,%1},[%2];" : "=r"(v.x), "=r"(v.y) : "r"(addr));
    return v;
}
#define CP_A16(dst, src) asm volatile("cp.async.cg.shared.global [%0],[%1],16;" :: "r"(dst), "l"(src))
#define CP_A4(dst, src)  asm volatile("cp.async.ca.shared.global [%0],[%1],4;"  :: "r"(dst), "l"(src))
#define CP_COMMIT()      asm volatile("cp.async.commit_group;" ::: "memory")
#define CP_WAIT0()       asm volatile("cp.async.wait_group 0;" ::: "memory")
#define CP_WAIT1()       asm volatile("cp.async.wait_group 1;" ::: "memory")

__device__ __forceinline__ void mma_tf32(float* c, const uint32_t* a, const uint32_t* b) {
    asm volatile(
        "mma.sync.aligned.m16n8k8.row.col.f32.tf32.tf32.f32 "
        "{%0,%1,%2,%3},{%4,%5,%6,%7},{%8,%9},{%0,%1,%2,%3};"
        : "+f"(c[0]), "+f"(c[1]), "+f"(c[2]), "+f"(c[3])
        : "r"(a[0]), "r"(a[1]), "r"(a[2]), "r"(a[3]), "r"(b[0]), "r"(b[1]));
}

// ---------------- prep kernels ----------------
__global__ void prep_x4(const float4* __restrict__ x) {
    int i = blockIdx.x * 256 + threadIdx.x;
    float4 v = x[i];
    uint4 o;
    o.x = f2tf32(v.x); o.y = f2tf32(v.y); o.z = f2tf32(v.z); o.w = f2tf32(v.w);
    ((uint4*)g_x)[i] = o;
}

__global__ void prep_w(const float* __restrict__ w) {
    int idx = blockIdx.x * 256 + threadIdx.x;   // 73728
    int h   = idx & 1;
    int p   = (idx >> 1) & 3;
    int oc  = (idx >> 3) & 127;
    int kb  = (idx >> 10) & 1;
    int s   = idx >> 11;
    int off  = s >> 2;
    int cblk = s & 3;
    int c = cblk * 16 + kb * 8 + p + 4 * h;
    g_a2[idx] = f2tf32(w[oc * 576 + c * 9 + off]);
}

// ---------------- main kernel ----------------
__global__ __launch_bounds__(256, 2) void conv_main(float* __restrict__ out) {
    extern __shared__ __align__(16) uint32_t sm[];

    const int tid  = threadIdx.x;
    const int lane = tid & 31;
    const int warp = tid >> 5;
    const int wm   = warp >> 2;        // 0..1 : oc half
    const int wn   = warp & 3;         // 0..3 : n quarter

    const int b  = blockIdx.y;
    const int n0 = blockIdx.x * 128;

    const uint32_t smem_b = cvta_s(sm);

    // ---- per-thread staging descriptors ----
    const uint32_t* xb = g_x + (size_t)b * (NC*NH*NW);
    uint32_t b_dstw[8];                 // word offset within B region
    uint32_t b_srco[8];                 // word offset within xb (kk*4096 + pos)
    #pragma unroll
    for (int j = 0; j < 8; ++j) {
        int e  = tid + j * 256;
        int kk = e >> 7;
        int nl = e & 127;
        int n  = n0 + nl; if (n > NPB-1) n = NPB-1;
        int ho = n / WO;
        int wo = n - ho * WO;
        b_dstw[j] = (uint32_t)((kk >> 3) * BKB + (kk & 3) * BKQ + nl * 2 + ((kk >> 2) & 1));
        b_srco[j] = (uint32_t)(kk * (NH*NW) + ho * NW + wo);
    }

    float acc[4][4][4];
    #pragma unroll
    for (int mi = 0; mi < 4; ++mi)
        #pragma unroll
        for (int ni = 0; ni < 4; ++ni)
            #pragma unroll
            for (int q = 0; q < 4; ++q) acc[mi][ni][q] = 0.0f;

    // fragment base addresses (bytes), relative to buffer start
    const uint32_t a_fw = ((uint32_t)(wm * 64 + (lane >> 2)) * 8 + (lane & 3) * 2) * 4;
    const uint32_t b_fw = (AW + (uint32_t)(lane & 3) * BKQ + (wn * 32 + (lane >> 2)) * 2) * 4;

    // ---- stage issuer ----
    auto issue_stage = [&](int s, uint32_t bufw) {
        const int off  = s >> 2;
        const int cblk = s & 3;
        const int kh   = off / 3;
        const int kw   = off - kh * 3;
        const uint32_t adst = smem_b + bufw * 4 + (uint32_t)tid * 16;
        const uint32_t* asrc = g_a2 + s * AW + tid * 4;
        CP_A16(adst, asrc);
        CP_A16(adst + 4096, asrc + 1024);
        const uint32_t soff = (uint32_t)(cblk * 16 * (NH*NW) + kh * NW + kw);
        const uint32_t bbase = smem_b + (bufw + AW) * 4;
        #pragma unroll
        for (int j = 0; j < 8; ++j)
            CP_A4(bbase + b_dstw[j] * 4, (const char*)(xb + b_srco[j] + soff));
        CP_COMMIT();
    };

    // prologue: stages 0,1 into buffers 0,1
    issue_stage(0, 0);
    issue_stage(1, STGW);

    uint32_t bufw  = 0;            // buffer of stage s
    uint32_t bufw2 = 2 * STGW;     // buffer of stage s+2

    #pragma unroll 1
    for (int s = 0; s < NSTG; ++s) {
        if (s == NSTG - 1) { CP_WAIT0(); } else { CP_WAIT1(); }
        __syncthreads();

        if (s + 2 < NSTG) issue_stage(s + 2, bufw2);

        const uint32_t abase = smem_b + bufw * 4 + a_fw;
        const uint32_t bbase = smem_b + bufw * 4 + b_fw;

        #pragma unroll
        for (int kb = 0; kb < 2; ++kb) {
            uint32_t af[4][4], bf[4][2];
            const uint32_t ak = abase + (uint32_t)kb * 1024 * 4;
            const uint32_t bk = bbase + (uint32_t)kb * BKB * 4;
            #pragma unroll
            for (int mi = 0; mi < 4; ++mi) {
                uint2 t0 = lds64(ak + (uint32_t)mi * 128 * 4);
                uint2 t1 = lds64(ak + (uint32_t)(mi * 128 + 64) * 4);
                af[mi][0] = t0.x; af[mi][2] = t0.y;
                af[mi][1] = t1.x; af[mi][3] = t1.y;
            }
            #pragma unroll
            for (int ni = 0; ni < 4; ++ni) {
                uint2 t = lds64(bk + (uint32_t)ni * 16 * 4);
                bf[ni][0] = t.x; bf[ni][1] = t.y;
            }
            #pragma unroll
            for (int mi = 0; mi < 4; ++mi)
                #pragma unroll
                for (int ni = 0; ni < 4; ++ni)
                    mma_tf32(acc[mi][ni], af[mi], bf[ni]);
        }

        // rotate buffers
        bufw  += STGW; if (bufw  == NBUF * STGW) bufw  = 0;
        bufw2 += STGW; if (bufw2 == NBUF * STGW) bufw2 = 0;
    }

    // ---- epilogue ----
    #pragma unroll
    for (int mi = 0; mi < 4; ++mi) {
        #pragma unroll
        for (int ni = 0; ni < 4; ++ni) {
            const int ocr = wm * 64 + mi * 16 + (lane >> 2);
            const int n   = n0 + wn * 32 + ni * 8 + 2 * (lane & 3);
            if (n < NPB) {
                float* p0 = out + ((size_t)ocr * NB + b) * NPB + n;
                *(float2*)p0 = make_float2(acc[mi][ni][0], acc[mi][ni][1]);
                float* p1 = out + ((size_t)(ocr + 8) * NB + b) * NPB + n;
                *(float2*)p1 = make_float2(acc[mi][ni][2], acc[mi][ni][3]);
            }
        }
    }
}

// ---------------- launch ----------------
extern "C" void kernel_launch(void* const* d_in, const int* in_sizes, int n_in,
                              void* d_out, int out_size) {
    const float* x = (const float*)d_in[0];
    const float* w = (const float*)d_in[1];
    float* out = (float*)d_out;

    cudaFuncSetAttribute(conv_main, cudaFuncAttributeMaxDynamicSharedMemorySize, SMEMB);

    prep_x4<<<(NB*NC*NH*NW)/4/256, 256>>>((const float4*)x);
    prep_w<<<(NSTG*2048)/256, 256>>>(w);
    conv_main<<<dim3(NTILE, NB), 256, SMEMB>>>(out);
}

// round 5
// speedup vs baseline: 6.3439x; 1.4823x over previous
#include <cuda_runtime.h>
#include <cstdint>

#define NB   32
#define NC   64
#define NH   64
#define NW   64
#define NOC  128
#define HO   62
#define WO   62
#define NPB  (HO*WO)            // 3844
#define NTILE 31
#define NSTG 36                 // K stages of 16 (K = 9*64)

// packed fp16 x: word = (ch even fp16 lo, ch odd fp16 hi); layout [b][c2 32][h][w]
__device__ __align__(16) uint32_t g_x16[NB*32*NH*NW];        // 16.78 MB
// pre-arranged fp16 A: [stage 36][oc 128][slot 8]; slot=(p&3)*2+(p>>2), word=(ch 2p, ch 2p+1)
__device__ __align__(16) uint32_t g_a16[NSTG*1024];          // 147.5 KB

// ---- SMEM geometry (words, per buffer) ----
#define AW    1024              // A: 128 oc x 8 slots
#define BW    1024              // B: 128 n  x 8 slots
#define STGW  (AW + BW)         // 2048
#define NBUF  3

// ---------------- PTX helpers ----------------
__device__ __forceinline__ uint32_t cvta_s(const void* p) {
    uint32_t a;
    asm("{ .reg .u64 t; cvta.to.shared.u64 t, %1; cvt.u32.u64 %0, t; }" : "=r"(a) : "l"(p));
    return a;
}
__device__ __forceinline__ uint32_t pack_h2(float even, float odd) {
    uint32_t d;
    asm("cvt.rn.f16x2.f32 %0, %1, %2;" : "=r"(d) : "f"(odd), "f"(even));  // lo=even, hi=odd
    return d;
}
__device__ __forceinline__ uint2 lds64(uint32_t addr) {
    uint2 v;
    asm volatile("ld.shared.v2.b32 {%0,%1},[%2];" : "=r"(v.x), "=r"(v.y) : "r"(addr));
    return v;
}
#define CP_A16(dst, src) asm volatile("cp.async.cg.shared.global [%0],[%1],16;" :: "r"(dst), "l"(src))
#define CP_A4(dst, src)  asm volatile("cp.async.ca.shared.global [%0],[%1],4;"  :: "r"(dst), "l"(src))
#define CP_COMMIT()      asm volatile("cp.async.commit_group;" ::: "memory")
#define CP_WAIT0()       asm volatile("cp.async.wait_group 0;" ::: "memory")
#define CP_WAIT1()       asm volatile("cp.async.wait_group 1;" ::: "memory")

__device__ __forceinline__ void mma_f16(float* c, const uint32_t* a, const uint32_t* b) {
    asm volatile(
        "mma.sync.aligned.m16n8k16.row.col.f32.f16.f16.f32 "
        "{%0,%1,%2,%3},{%4,%5,%6,%7},{%8,%9},{%0,%1,%2,%3};"
        : "+f"(c[0]), "+f"(c[1]), "+f"(c[2]), "+f"(c[3])
        : "r"(a[0]), "r"(a[1]), "r"(a[2]), "r"(a[3]), "r"(b[0]), "r"(b[1]));
}

// ---------------- prep kernels ----------------
// pack channel pairs: 4 positions per thread (float4 from even + odd channel)
__global__ void prep_x16(const float* __restrict__ x) {
    int t = blockIdx.x * 256 + threadIdx.x;      // 1,048,576 total
    int b    = t >> 15;
    int r    = t & 32767;
    int c2   = r >> 10;
    int pos4 = r & 1023;
    const float4* pe = (const float4*)(x + ((size_t)b * NC + 2*c2)     * (NH*NW)) + pos4;
    const float4* po = (const float4*)(x + ((size_t)b * NC + 2*c2 + 1) * (NH*NW)) + pos4;
    float4 e = *pe, o = *po;
    uint4 d;
    d.x = pack_h2(e.x, o.x);
    d.y = pack_h2(e.y, o.y);
    d.z = pack_h2(e.z, o.z);
    d.w = pack_h2(e.w, o.w);
    ((uint4*)g_x16)[((size_t)b * 32 + c2) * 1024 + pos4] = d;
}

__global__ void prep_w(const float* __restrict__ w) {
    int idx = blockIdx.x * 256 + threadIdx.x;    // 36864
    int slot = idx & 7;
    int oc   = (idx >> 3) & 127;
    int s    = idx >> 10;
    int off  = s >> 2;
    int cblk = s & 3;
    int p    = (slot >> 1) + 4 * (slot & 1);
    int ce   = cblk * 16 + 2 * p;
    g_a16[idx] = pack_h2(w[oc * 576 + ce * 9 + off], w[oc * 576 + (ce + 1) * 9 + off]);
}

// ---------------- main kernel ----------------
__global__ __launch_bounds__(256, 2) void conv_main(float* __restrict__ out) {
    __shared__ __align__(16) uint32_t sm[NBUF * STGW];       // 24 KB

    const int tid  = threadIdx.x;
    const int lane = tid & 31;
    const int warp = tid >> 5;
    const int wm   = warp >> 2;        // 0..1 : oc half
    const int wn   = warp & 3;         // 0..3 : n quarter

    const int b  = blockIdx.y;
    const int n0 = blockIdx.x * 128;

    const uint32_t smem_b = cvta_s(sm);

    // ---- per-thread B staging descriptors (4 words / stage) ----
    const uint32_t* xb = g_x16 + (size_t)b * (32 * NH * NW);
    uint32_t b_dstw[4], b_srco[4];
    #pragma unroll
    for (int j = 0; j < 4; ++j) {
        int e  = tid + j * 256;
        int kp = e >> 7;               // pair row 0..7
        int nl = e & 127;
        int n  = n0 + nl; if (n > NPB-1) n = NPB-1;
        int ho = n / WO;
        int wo = n - ho * WO;
        b_dstw[j] = (uint32_t)(AW + nl * 8 + (kp & 3) * 2 + (kp >> 2));
        b_srco[j] = (uint32_t)(kp * (NH*NW) + ho * NW + wo);
    }

    float acc[4][4][4];
    #pragma unroll
    for (int mi = 0; mi < 4; ++mi)
        #pragma unroll
        for (int ni = 0; ni < 4; ++ni)
            #pragma unroll
            for (int q = 0; q < 4; ++q) acc[mi][ni][q] = 0.0f;

    // fragment base byte-offsets within a buffer
    const uint32_t a_fw = ((uint32_t)(wm * 64 + (lane >> 2)) * 8 + (lane & 3) * 2) * 4;
    const uint32_t b_fw = (AW + (uint32_t)(wn * 32 + (lane >> 2)) * 8 + (lane & 3) * 2) * 4;

    auto issue_stage = [&](int s, uint32_t bufw) {
        const int off  = s >> 2;
        const int cblk = s & 3;
        const int kh   = off / 3;
        const int kw   = off - kh * 3;
        // A: 1024 words, 1x16B per thread
        CP_A16(smem_b + bufw * 4 + (uint32_t)tid * 16, g_a16 + s * AW + tid * 4);
        // B: 1024 words, 4x4B per thread
        const uint32_t soff = (uint32_t)(cblk * 8 * (NH*NW) + kh * NW + kw);
        #pragma unroll
        for (int j = 0; j < 4; ++j)
            CP_A4(smem_b + (bufw + b_dstw[j]) * 4, (const char*)(xb + b_srco[j] + soff));
        CP_COMMIT();
    };

    issue_stage(0, 0);
    issue_stage(1, STGW);

    uint32_t bufw  = 0;
    uint32_t bufw2 = 2 * STGW;

    #pragma unroll 1
    for (int s = 0; s < NSTG; ++s) {
        if (s == NSTG - 1) { CP_WAIT0(); } else { CP_WAIT1(); }
        __syncthreads();

        if (s + 2 < NSTG) issue_stage(s + 2, bufw2);

        const uint32_t abase = smem_b + bufw * 4 + a_fw;
        const uint32_t bbase = smem_b + bufw * 4 + b_fw;

        uint32_t af[4][4], bf[4][2];
        #pragma unroll
        for (int mi = 0; mi < 4; ++mi) {
            uint2 t0 = lds64(abase + (uint32_t)mi * 128 * 4);         // row r
            uint2 t1 = lds64(abase + (uint32_t)(mi * 128 + 64) * 4);  // row r+8
            af[mi][0] = t0.x; af[mi][1] = t1.x; af[mi][2] = t0.y; af[mi][3] = t1.y;
        }
        #pragma unroll
        for (int ni = 0; ni < 4; ++ni) {
            uint2 t = lds64(bbase + (uint32_t)ni * 64 * 4);
            bf[ni][0] = t.x; bf[ni][1] = t.y;
        }
        #pragma unroll
        for (int mi = 0; mi < 4; ++mi)
            #pragma unroll
            for (int ni = 0; ni < 4; ++ni)
                mma_f16(acc[mi][ni], af[mi], bf[ni]);

        bufw  += STGW; if (bufw  == NBUF * STGW) bufw  = 0;
        bufw2 += STGW; if (bufw2 == NBUF * STGW) bufw2 = 0;
    }

    // ---- epilogue: rows = oc, cols = n ; out[(oc*NB + b)*NPB + n] ----
    #pragma unroll
    for (int mi = 0; mi < 4; ++mi) {
        #pragma unroll
        for (int ni = 0; ni < 4; ++ni) {
            const int ocr = wm * 64 + mi * 16 + (lane >> 2);
            const int n   = n0 + wn * 32 + ni * 8 + 2 * (lane & 3);
            if (n < NPB) {
                float* p0 = out + ((size_t)ocr * NB + b) * NPB + n;
                *(float2*)p0 = make_float2(acc[mi][ni][0], acc[mi][ni][1]);
                float* p1 = out + ((size_t)(ocr + 8) * NB + b) * NPB + n;
                *(float2*)p1 = make_float2(acc[mi][ni][2], acc[mi][ni][3]);
            }
        }
    }
}

// ---------------- launch ----------------
extern "C" void kernel_launch(void* const* d_in, const int* in_sizes, int n_in,
                              void* d_out, int out_size) {
    const float* x = (const float*)d_in[0];
    const float* w = (const float*)d_in[1];
    float* out = (float*)d_out;

    prep_x16<<<4096, 256>>>(x);
    prep_w<<<144, 256>>>(w);
    conv_main<<<dim3(NTILE, NB), 256>>>(out);
}

// round 6
// speedup vs baseline: 10.4773x; 1.6515x over previous
#include <cuda_runtime.h>
#include <cstdint>

#define NB   32
#define NH   64
#define NW   64
#define HO   62
#define WO   62
#define NPB  (HO*WO)            // 3844

// packed fp16 x: word = (ch even lo, ch odd hi); layout [b][c2 32][h][w], +pad
__device__ __align__(16) uint32_t g_x16[NB*32*NH*NW + 16];   // 16.78 MB
// A: [g 12][kw 3][oc 128][slot 8] fp16x2
__device__ __align__(16) uint32_t g_a16[36*1024];            // 147.5 KB

// ---- SMEM geometry (words per buffer) ----
#define AWRD  3072              // 3 kw tiles x 128 oc x 8 slots
#define BWRD  1088              // 8 c2 x 2 rows x 68
#define STW   (AWRD + BWRD)     // 4160
// buffers: 2 x 4160 words = 33280 B

// ---------------- PTX helpers ----------------
__device__ __forceinline__ uint32_t cvta_s(const void* p) {
    uint32_t a;
    asm("{ .reg .u64 t; cvta.to.shared.u64 t, %1; cvt.u32.u64 %0, t; }" : "=r"(a) : "l"(p));
    return a;
}
__device__ __forceinline__ uint32_t pack_h2(float even, float odd) {
    uint32_t d;
    asm("cvt.rn.f16x2.f32 %0, %1, %2;" : "=r"(d) : "f"(odd), "f"(even));
    return d;
}
__device__ __forceinline__ uint2 lds64(uint32_t addr) {
    uint2 v;
    asm volatile("ld.shared.v2.b32 {%0,%1},[%2];" : "=r"(v.x), "=r"(v.y) : "r"(addr));
    return v;
}
__device__ __forceinline__ uint32_t lds32(uint32_t addr) {
    uint32_t v;
    asm volatile("ld.shared.b32 %0,[%1];" : "=r"(v) : "r"(addr));
    return v;
}
#define CP_A16(dst, src) asm volatile("cp.async.cg.shared.global [%0],[%1],16;" :: "r"(dst), "l"(src))
#define CP_COMMIT()      asm volatile("cp.async.commit_group;" ::: "memory")
#define CP_WAIT0()       asm volatile("cp.async.wait_group 0;" ::: "memory")
#define CP_WAIT1()       asm volatile("cp.async.wait_group 1;" ::: "memory")

__device__ __forceinline__ void mma_f16(float* c, const uint32_t* a, const uint32_t* b) {
    asm volatile(
        "mma.sync.aligned.m16n8k16.row.col.f32.f16.f16.f32 "
        "{%0,%1,%2,%3},{%4,%5,%6,%7},{%8,%9},{%0,%1,%2,%3};"
        : "+f"(c[0]), "+f"(c[1]), "+f"(c[2]), "+f"(c[3])
        : "r"(a[0]), "r"(a[1]), "r"(a[2]), "r"(a[3]), "r"(b[0]), "r"(b[1]));
}

// ---------------- prep kernels ----------------
__global__ void prep_x16(const float* __restrict__ x) {
    int t = blockIdx.x * 256 + threadIdx.x;      // 1,048,576
    int b    = t >> 15;
    int r    = t & 32767;
    int c2   = r >> 10;
    int pos4 = r & 1023;
    const float4* pe = (const float4*)(x + ((size_t)b * 64 + 2*c2)     * (NH*NW)) + pos4;
    const float4* po = (const float4*)(x + ((size_t)b * 64 + 2*c2 + 1) * (NH*NW)) + pos4;
    float4 e = *pe, o = *po;
    uint4 d;
    d.x = pack_h2(e.x, o.x);
    d.y = pack_h2(e.y, o.y);
    d.z = pack_h2(e.z, o.z);
    d.w = pack_h2(e.w, o.w);
    ((uint4*)g_x16)[((size_t)b * 32 + c2) * 1024 + pos4] = d;
}

__global__ void prep_w(const float* __restrict__ w) {
    int idx = blockIdx.x * 256 + threadIdx.x;    // 36864
    int slot = idx & 7;
    int oc   = (idx >> 3) & 127;
    int sA   = idx >> 10;          // 0..35 = g*3 + kw
    int g    = sA / 3;
    int kw   = sA - g * 3;
    int kh   = g >> 2;
    int cblk = g & 3;
    int off  = kh * 3 + kw;
    int p    = (slot >> 1) + 4 * (slot & 1);
    int ce   = cblk * 16 + 2 * p;
    g_a16[idx] = pack_h2(w[oc * 576 + ce * 9 + off], w[oc * 576 + (ce + 1) * 9 + off]);
}

// ---------------- main kernel ----------------
__global__ __launch_bounds__(256, 2) void conv_main(float* __restrict__ out) {
    __shared__ __align__(16) uint32_t sm[2 * STW];           // 33280 B

    const int tid  = threadIdx.x;
    const int lane = tid & 31;
    const int warp = tid >> 5;
    const int wm   = warp >> 2;        // 0..1 : oc half
    const int wn   = warp & 3;         // 0..3 : n quarter
    const int rW   = wn >> 1;          // output row within tile
    const int cW   = (wn & 1) * 32;    // wo base

    const int b   = blockIdx.y;
    const int ho0 = blockIdx.x * 2;    // 2 output rows per CTA

    const uint32_t smem_b = cvta_s(sm);
    const uint32_t* xb = g_x16 + (size_t)b * (32 * NH * NW);

    // ---- B staging descriptors: 272 x 16B ops; op i: run=i/17, q=i%17 ----
    uint32_t bd0, bs0, bd1 = 0, bs1 = 0;
    {
        int i = tid, run = i / 17, q = i - run * 17;
        int c2 = run >> 1, r = run & 1;
        bd0 = (uint32_t)(AWRD + c2 * 136 + r * 68 + q * 4);
        bs0 = (uint32_t)(c2 * 4096 + (ho0 + r) * 64 + q * 4);
        if (tid < 16) {
            int i2 = 256 + tid, run2 = i2 / 17, q2 = i2 - run2 * 17;
            int c22 = run2 >> 1, r2 = run2 & 1;
            bd1 = (uint32_t)(AWRD + c22 * 136 + r2 * 68 + q2 * 4);
            bs1 = (uint32_t)(c22 * 4096 + (ho0 + r2) * 64 + q2 * 4);
        }
    }

    float acc[4][4][4];
    #pragma unroll
    for (int mi = 0; mi < 4; ++mi)
        #pragma unroll
        for (int ni = 0; ni < 4; ++ni)
            #pragma unroll
            for (int q = 0; q < 4; ++q) acc[mi][ni][q] = 0.0f;

    const uint32_t a_fw = ((uint32_t)(wm * 64 + (lane >> 2)) * 8 + (lane & 3) * 2) * 4;
    const uint32_t b_fw = (uint32_t)(AWRD + (lane & 3) * 136 + rW * 68 + cW + (lane >> 2)) * 4;

    auto issue_big = [&](int g, uint32_t bufw) {
        const int kh   = g >> 2;
        const int cblk = g & 3;
        // A: 3072 words, 3 x 16B per thread (linear memcpy)
        const uint4* asrc = (const uint4*)(g_a16 + g * AWRD) + tid;
        const uint32_t adst = smem_b + bufw * 4 + (uint32_t)tid * 16;
        CP_A16(adst,        asrc);
        CP_A16(adst + 4096, asrc + 256);
        CP_A16(adst + 8192, asrc + 512);
        // B: 272 x 16B
        const uint32_t soff = (uint32_t)(cblk * 8 * 4096 + kh * 64);
        CP_A16(smem_b + (bufw + bd0) * 4, (const char*)(xb + bs0 + soff));
        if (tid < 16)
            CP_A16(smem_b + (bufw + bd1) * 4, (const char*)(xb + bs1 + soff));
        CP_COMMIT();
    };

    issue_big(0, 0);
    uint32_t bufw = 0;

    #pragma unroll 1
    for (int g = 0; g < 12; ++g) {
        if (g + 1 < 12) { issue_big(g + 1, bufw ^ STW); CP_WAIT1(); }
        else            { CP_WAIT0(); }
        __syncthreads();

        const uint32_t abase0 = smem_b + bufw * 4 + a_fw;
        const uint32_t bbase0 = smem_b + bufw * 4 + b_fw;

        #pragma unroll
        for (int kw = 0; kw < 3; ++kw) {
            const uint32_t abase = abase0 + (uint32_t)kw * 4096;
            const uint32_t bbase = bbase0 + (uint32_t)kw * 4;

            uint32_t af[4][4], bf[4][2];
            #pragma unroll
            for (int mi = 0; mi < 4; ++mi) {
                uint2 t0 = lds64(abase + (uint32_t)mi * 512);
                uint2 t1 = lds64(abase + (uint32_t)(mi * 512 + 256));
                af[mi][0] = t0.x; af[mi][1] = t1.x; af[mi][2] = t0.y; af[mi][3] = t1.y;
            }
            #pragma unroll
            for (int ni = 0; ni < 4; ++ni) {
                bf[ni][0] = lds32(bbase + (uint32_t)ni * 32);
                bf[ni][1] = lds32(bbase + (uint32_t)ni * 32 + 2176);
            }
            #pragma unroll
            for (int mi = 0; mi < 4; ++mi)
                #pragma unroll
                for (int ni = 0; ni < 4; ++ni)
                    mma_f16(acc[mi][ni], af[mi], bf[ni]);
        }
        __syncthreads();
        bufw ^= STW;
    }

    // ---- epilogue ----
    const int orow = ho0 + rW;
    #pragma unroll
    for (int mi = 0; mi < 4; ++mi) {
        #pragma unroll
        for (int ni = 0; ni < 4; ++ni) {
            const int ocr = wm * 64 + mi * 16 + (lane >> 2);
            const int wo  = cW + ni * 8 + 2 * (lane & 3);
            if (wo < WO) {
                const size_t base = (size_t)orow * WO + wo;
                float* p0 = out + ((size_t)ocr * NB + b) * NPB + base;
                *(float2*)p0 = make_float2(acc[mi][ni][0], acc[mi][ni][1]);
                float* p1 = out + ((size_t)(ocr + 8) * NB + b) * NPB + base;
                *(float2*)p1 = make_float2(acc[mi][ni][2], acc[mi][ni][3]);
            }
        }
    }
}

// ---------------- launch ----------------
extern "C" void kernel_launch(void* const* d_in, const int* in_sizes, int n_in,
                              void* d_out, int out_size) {
    const float* x = (const float*)d_in[0];
    const float* w = (const float*)d_in[1];
    float* out = (float*)d_out;

    prep_x16<<<4096, 256>>>(x);
    prep_w<<<144, 256>>>(w);
    conv_main<<<dim3(31, NB), 256>>>(out);
}